// round 7
// baseline (speedup 1.0000x reference)
#include <cuda_runtime.h>
#include <cuda_bf16.h>
#include <cstdint>

// pooled[i][j] = 1.0 if any k in [j-25, j+25] (in-range) has |in[i]-w[k]| < 0.1
// N=1024, M=262144 -> 1 GiB fp32 output; HBM write roofline target.
//
// R7 vs R6 (149.9us, DRAM 86.4%):
//  - ROWS_PER_BLOCK 8->4 (grid 8192): kills tail-wave quantization
//    (7.5 waves w/ half-full tail -> ~15 waves w/ ~full tail)
//  - store redistribution in 4 shuffles (8 bits each) instead of 8,
//    each expanding to two float4 stores
//  - unchanged: warp-independent segments, ballot halos, packed-f32x2
//    sign-bit mask build, log-step dilation, streaming STG.128

#define THREADS 256
#define WPT 32                       // pooled bits per thread
#define SEG 1024                     // columns per warp
#define CHUNK (THREADS * WPT)        // 8192 columns per block
#define ROWS_PER_BLOCK 4
#define THRESH 0.1f
#define OOR_VAL 3.0e38f              // sentinel == -inf pad (never within 0.1)

// mask bit b = (vi - w[b])^2 < 0.01  (== |vi-w[b]| < 0.1 up to ulp-level boundary band)
__device__ __forceinline__ unsigned mask32_sq(unsigned long long vv,
                                              const unsigned long long* nwp,
                                              unsigned long long c2)
{
    unsigned m = 0;
    #pragma unroll
    for (int k = 15; k >= 0; --k) {
        unsigned long long d, s;
        asm("add.rn.f32x2 %0, %1, %2;" : "=l"(d) : "l"(vv), "l"(nwp[k]));
        asm("fma.rn.f32x2 %0, %1, %1, %2;" : "=l"(s) : "l"(d), "l"(c2));
        const unsigned lo = (unsigned)s;
        const unsigned hi = (unsigned)(s >> 32);
        m = __funnelshift_l(hi, m, 1);   // (m<<1) | sign : weight 2k+1
        m = __funnelshift_l(lo, m, 1);   // (m<<1) | sign : weight 2k
    }
    return m;
}

__global__ __launch_bounds__(THREADS)
void cll_pool_kernel(const float* __restrict__ in_feat,
                     const float* __restrict__ weights,
                     float* __restrict__ out,
                     int N, int M)
{
    const int t = threadIdx.x;
    const int lane = t & 31;
    const int warp = t >> 5;
    const int segbase = blockIdx.x * CHUNK + warp * SEG;   // this warp's first column

    // ---- one-time loads: this thread's 32 weights -> 16 packed negated pairs ----
    unsigned long long nwp[16];
    {
        const int g0 = segbase + lane * WPT;
        float wv[32];
        if (g0 + WPT <= M) {
            const float4* wp = reinterpret_cast<const float4*>(weights + g0);
            #pragma unroll
            for (int g = 0; g < 8; ++g) {
                float4 q = wp[g];
                wv[4*g+0] = q.x; wv[4*g+1] = q.y; wv[4*g+2] = q.z; wv[4*g+3] = q.w;
            }
        } else {
            #pragma unroll
            for (int b = 0; b < 32; ++b) {
                int gg = g0 + b;
                wv[b] = (gg < M) ? weights[gg] : OOR_VAL;
            }
        }
        #pragma unroll
        for (int k = 0; k < 16; ++k) {
            unsigned lo = __float_as_uint(-wv[2*k]);
            unsigned hi = __float_as_uint(-wv[2*k+1]);
            nwp[k] = ((unsigned long long)hi << 32) | lo;
        }
    }
    // per-lane halo weights for the warp's segment edges
    float hwl, hwr;
    {
        int gl = segbase - 32 + lane;          // cols [segbase-32, segbase)
        int gr = segbase + SEG + lane;         // cols [segbase+SEG, segbase+SEG+32)
        hwl = (gl >= 0 && gl < M) ? __ldg(weights + gl) : OOR_VAL;
        hwr = (gr < M)            ? __ldg(weights + gr) : OOR_VAL;
    }

    const unsigned long long c2 =
        ((unsigned long long)__float_as_uint(-0.01f) << 32) | __float_as_uint(-0.01f);

    const int row0 = blockIdx.y * ROWS_PER_BLOCK;
    const int shamt8 = (lane & 3) * 8;         // byte within source pooled word
    const int srcbase8 = lane >> 2;            // source lane offset within 8-lane group

    #pragma unroll 1
    for (int r = 0; r < ROWS_PER_BLOCK; ++r) {
        int i = row0 + r;
        if (i >= N) i = N - 1;
        const float vi = __ldg(&in_feat[i]);

        // ---- mask word + halo words (warp-local, no smem, no block sync) ----
        const unsigned long long vv =
            ((unsigned long long)__float_as_uint(vi) << 32) | __float_as_uint(vi);
        const unsigned m = mask32_sq(vv, nwp, c2);
        const unsigned hl = __ballot_sync(0xFFFFFFFFu, fabsf(vi - hwl) < THRESH);
        const unsigned hr = __ballot_sync(0xFFFFFFFFu, fabsf(vi - hwr) < THRESH);

        unsigned wm1 = __shfl_up_sync(0xFFFFFFFFu, m, 1);
        unsigned wp1 = __shfl_down_sync(0xFFFFFFFFu, m, 1);
        if (lane == 0)  wm1 = hl;
        if (lane == 31) wp1 = hr;

        // ---- width-51 sliding OR (radius 25) via log-step dilation ----
        unsigned long long lo = (unsigned long long)wm1 | ((unsigned long long)m << 32);
        unsigned long long hi = (unsigned long long)m   | ((unsigned long long)wp1 << 32);
        hi |= hi >> 1;  hi |= hi >> 2;  hi |= hi >> 4;  hi |= hi >> 8;  hi |= hi >> 10;
        lo |= lo << 1;  lo |= lo << 2;  lo |= lo << 4;  lo |= lo << 8;  lo |= lo << 10;
        const unsigned p = (unsigned)hi | (unsigned)(lo >> 32);

        // ---- coalesced emit: 4 shuffles, 8 bits -> two float4 stores each ----
        // step s covers cols [s*256, s*256+256): lane t writes cols s*256 + t*8 .. +8
        // bits come from lane (s*8 + t/4)'s pooled word, byte (t%4)
        float* wout = out + (size_t)i * (size_t)M + segbase;
        #pragma unroll
        for (int s = 0; s < 4; ++s) {
            unsigned src = __shfl_sync(0xFFFFFFFFu, p, s * 8 + srcbase8);
            unsigned bits = src >> shamt8;     // 8 pooled bits for this lane's 8 cols
            float4 v0, v1;
            v0.x = __uint_as_float((bits &   1u) * 0x3F800000u);
            v0.y = __uint_as_float((bits &   2u) * 0x1FC00000u);
            v0.z = __uint_as_float((bits &   4u) * 0x0FE00000u);
            v0.w = __uint_as_float((bits &   8u) * 0x07F00000u);
            v1.x = __uint_as_float((bits &  16u) * 0x03F80000u);
            v1.y = __uint_as_float((bits &  32u) * 0x01FC0000u);
            v1.z = __uint_as_float((bits &  64u) * 0x00FE0000u);
            v1.w = __uint_as_float((bits & 128u) * 0x007F0000u);
            float4* dst = reinterpret_cast<float4*>(wout + s * 256) + lane * 2;
            __stcs(dst,     v0);
            __stcs(dst + 1, v1);
        }
    }
}

extern "C" void kernel_launch(void* const* d_in, const int* in_sizes, int n_in,
                              void* d_out, int out_size)
{
    const float* in_feat = (const float*)d_in[0];   // 1024 elements
    const float* weights = (const float*)d_in[1];   // 262144 elements
    float* out = (float*)d_out;

    const int N = in_sizes[0];
    const int M = in_sizes[1];

    dim3 grid((M + CHUNK - 1) / CHUNK, (N + ROWS_PER_BLOCK - 1) / ROWS_PER_BLOCK);
    cll_pool_kernel<<<grid, THREADS>>>(in_feat, weights, out, N, M);
}

// round 8
// speedup vs baseline: 1.2745x; 1.2745x over previous
#include <cuda_runtime.h>
#include <cuda_bf16.h>
#include <cstdint>

// pooled[i][j] = 1.0 if any k in [j-25, j+25] (in-range) has |in[i]-w[k]| < 0.1
// N=1024, M=262144 -> 1 GiB fp32 output; HBM write roofline target.
//
// R8:
//  - REVERT R7's interleaved two-float4 store (it halved line density per
//    STG.128: lanes wrote [t*32, t*32+16) -> 2x wavefronts, DRAM 86->61%).
//    Back to R6's dense 8-shuffle emit (lane*16B within each 512B step).
//  - persistent one-wave grid: (32 chunks) x (SMs*blocksPerSM/32) blocks,
//    each block keeps its chunk (weights packed in regs ONCE) and strides
//    over rows -> zero wave quantization, weight reload amortized over ~54
//    rows instead of 8.
//  - unchanged: warp-independent segments, ballot halos, packed-f32x2
//    sign-bit mask build, log-step dilation, streaming STG.128.

#define THREADS 256
#define WPT 32                       // pooled bits per thread
#define SEG 1024                     // columns per warp
#define CHUNK (THREADS * WPT)        // 8192 columns per block
#define THRESH 0.1f
#define OOR_VAL 3.0e38f              // sentinel == -inf pad (never within 0.1)

// mask bit b = (vi - w[b])^2 < 0.01  (== |vi-w[b]| < 0.1 up to ulp-level boundary band)
__device__ __forceinline__ unsigned mask32_sq(unsigned long long vv,
                                              const unsigned long long* nwp,
                                              unsigned long long c2)
{
    unsigned m = 0;
    #pragma unroll
    for (int k = 15; k >= 0; --k) {
        unsigned long long d, s;
        asm("add.rn.f32x2 %0, %1, %2;" : "=l"(d) : "l"(vv), "l"(nwp[k]));
        asm("fma.rn.f32x2 %0, %1, %1, %2;" : "=l"(s) : "l"(d), "l"(c2));
        const unsigned lo = (unsigned)s;
        const unsigned hi = (unsigned)(s >> 32);
        m = __funnelshift_l(hi, m, 1);   // (m<<1) | sign : weight 2k+1
        m = __funnelshift_l(lo, m, 1);   // (m<<1) | sign : weight 2k
    }
    return m;
}

__global__ __launch_bounds__(THREADS, 4)
void cll_pool_kernel(const float* __restrict__ in_feat,
                     const float* __restrict__ weights,
                     float* __restrict__ out,
                     int N, int M)
{
    const int t = threadIdx.x;
    const int lane = t & 31;
    const int warp = t >> 5;
    const int segbase = blockIdx.x * CHUNK + warp * SEG;   // this warp's first column

    // ---- one-time loads: this thread's 32 weights -> 16 packed negated pairs ----
    unsigned long long nwp[16];
    {
        const int g0 = segbase + lane * WPT;
        float wv[32];
        if (g0 + WPT <= M) {
            const float4* wp = reinterpret_cast<const float4*>(weights + g0);
            #pragma unroll
            for (int g = 0; g < 8; ++g) {
                float4 q = wp[g];
                wv[4*g+0] = q.x; wv[4*g+1] = q.y; wv[4*g+2] = q.z; wv[4*g+3] = q.w;
            }
        } else {
            #pragma unroll
            for (int b = 0; b < 32; ++b) {
                int gg = g0 + b;
                wv[b] = (gg < M) ? weights[gg] : OOR_VAL;
            }
        }
        #pragma unroll
        for (int k = 0; k < 16; ++k) {
            unsigned lo = __float_as_uint(-wv[2*k]);
            unsigned hi = __float_as_uint(-wv[2*k+1]);
            nwp[k] = ((unsigned long long)hi << 32) | lo;
        }
    }
    // per-lane halo weights for the warp's segment edges
    float hwl, hwr;
    {
        int gl = segbase - 32 + lane;          // cols [segbase-32, segbase)
        int gr = segbase + SEG + lane;         // cols [segbase+SEG, segbase+SEG+32)
        hwl = (gl >= 0 && gl < M) ? __ldg(weights + gl) : OOR_VAL;
        hwr = (gr < M)            ? __ldg(weights + gr) : OOR_VAL;
    }

    const unsigned long long c2 =
        ((unsigned long long)__float_as_uint(-0.01f) << 32) | __float_as_uint(-0.01f);

    const int shamt = (lane & 7) * 4;
    const int srcbase = lane >> 3;
    const int rstride = gridDim.y;

    #pragma unroll 1
    for (int i = blockIdx.y; i < N; i += rstride) {
        const float vi = __ldg(&in_feat[i]);

        // ---- mask word + halo words (warp-local, no smem, no block sync) ----
        const unsigned long long vv =
            ((unsigned long long)__float_as_uint(vi) << 32) | __float_as_uint(vi);
        const unsigned m = mask32_sq(vv, nwp, c2);
        const unsigned hl = __ballot_sync(0xFFFFFFFFu, fabsf(vi - hwl) < THRESH);
        const unsigned hr = __ballot_sync(0xFFFFFFFFu, fabsf(vi - hwr) < THRESH);

        unsigned wm1 = __shfl_up_sync(0xFFFFFFFFu, m, 1);
        unsigned wp1 = __shfl_down_sync(0xFFFFFFFFu, m, 1);
        if (lane == 0)  wm1 = hl;
        if (lane == 31) wp1 = hr;

        // ---- width-51 sliding OR (radius 25) via log-step dilation ----
        unsigned long long lo = (unsigned long long)wm1 | ((unsigned long long)m << 32);
        unsigned long long hi = (unsigned long long)m   | ((unsigned long long)wp1 << 32);
        hi |= hi >> 1;  hi |= hi >> 2;  hi |= hi >> 4;  hi |= hi >> 8;  hi |= hi >> 10;
        lo |= lo << 1;  lo |= lo << 2;  lo |= lo << 4;  lo |= lo << 8;  lo |= lo << 10;
        const unsigned p = (unsigned)hi | (unsigned)(lo >> 32);

        // ---- dense coalesced emit: step s = 512B, lane offset 16B ----
        float* wout = out + (size_t)i * (size_t)M + segbase;
        #pragma unroll
        for (int s = 0; s < 8; ++s) {
            unsigned src = __shfl_sync(0xFFFFFFFFu, p, s * 4 + srcbase);
            unsigned bits = src >> shamt;
            float4 v;
            v.x = __uint_as_float((bits & 1u) * 0x3F800000u);
            v.y = __uint_as_float((bits & 2u) * 0x1FC00000u);
            v.z = __uint_as_float((bits & 4u) * 0x0FE00000u);
            v.w = __uint_as_float((bits & 8u) * 0x07F00000u);
            __stcs(reinterpret_cast<float4*>(wout + s * 128) + lane, v);
        }
    }
}

extern "C" void kernel_launch(void* const* d_in, const int* in_sizes, int n_in,
                              void* d_out, int out_size)
{
    const float* in_feat = (const float*)d_in[0];   // 1024 elements
    const float* weights = (const float*)d_in[1];   // 262144 elements
    float* out = (float*)d_out;

    const int N = in_sizes[0];
    const int M = in_sizes[1];

    const int nchunks = (M + CHUNK - 1) / CHUNK;    // 32

    // exact one-wave persistent grid: SMs * resident-blocks-per-SM blocks total
    int dev = 0, sms = 148, bps = 4;
    cudaGetDevice(&dev);
    cudaDeviceGetAttribute(&sms, cudaDevAttrMultiProcessorCount, dev);
    cudaOccupancyMaxActiveBlocksPerMultiprocessor(&bps, cll_pool_kernel, THREADS, 0);
    if (bps < 1) bps = 1;
    int gy = (sms * bps) / nchunks;
    if (gy < 1) gy = 1;
    if (gy > N) gy = N;

    dim3 grid(nchunks, gy);
    cll_pool_kernel<<<grid, THREADS>>>(in_feat, weights, out, N, M);
}

// round 9
// speedup vs baseline: 1.3479x; 1.0576x over previous
#include <cuda_runtime.h>
#include <cuda_bf16.h>
#include <cstdint>

// pooled[i][j] = 1.0 if any k in [j-25, j+25] (in-range) has |in[i]-w[k]| < 0.1
// N=1024, M=262144 -> 1 GiB fp32 output; HBM write roofline target.
//
// R9 = R6 (best, 149.9us) + latency-chain fixes:
//  - REVERT R8's persistent one-wave grid (SM placement imbalance: 4.1
//    blocks/SM avg -> 5-vs-4 resident skew with no wave rebalancing;
//    DRAM 86->78%). Back to ROWS=8, grid 4096.
//  - mask build split into two independent 16-bit funnel-shift chains
//    (serial dep 128 -> ~64 cycles, 2x ILP)
//  - all 8 row inputs hoisted to registers before the row loop
//  - unchanged: warp-independent segments, ballot halos, log-step dilation,
//    dense shuffle-redistributed STG.128 streaming stores

#define THREADS 256
#define WPT 32                       // pooled bits per thread
#define SEG 1024                     // columns per warp
#define CHUNK (THREADS * WPT)        // 8192 columns per block
#define ROWS_PER_BLOCK 8
#define THRESH 0.1f
#define OOR_VAL 3.0e38f              // sentinel == -inf pad (never within 0.1)

// mask bit b = (vi - w[b])^2 < 0.01  (== |vi-w[b]| < 0.1 up to ulp-level boundary band)
// two independent 16-bit sign-accumulation chains for ILP
__device__ __forceinline__ unsigned mask32_sq(unsigned long long vv,
                                              const unsigned long long* nwp,
                                              unsigned long long c2)
{
    unsigned mlo = 0, mhi = 0;
    #pragma unroll
    for (int k = 7; k >= 0; --k) {
        unsigned long long d0, s0, d1, s1;
        asm("add.rn.f32x2 %0, %1, %2;" : "=l"(d0) : "l"(vv), "l"(nwp[k]));
        asm("add.rn.f32x2 %0, %1, %2;" : "=l"(d1) : "l"(vv), "l"(nwp[k + 8]));
        asm("fma.rn.f32x2 %0, %1, %1, %2;" : "=l"(s0) : "l"(d0), "l"(c2));
        asm("fma.rn.f32x2 %0, %1, %1, %2;" : "=l"(s1) : "l"(d1), "l"(c2));
        mlo = __funnelshift_l((unsigned)(s0 >> 32), mlo, 1);  // weight 2k+1
        mlo = __funnelshift_l((unsigned)s0,         mlo, 1);  // weight 2k
        mhi = __funnelshift_l((unsigned)(s1 >> 32), mhi, 1);  // weight 16+2k+1
        mhi = __funnelshift_l((unsigned)s1,         mhi, 1);  // weight 16+2k
    }
    return (mlo & 0xFFFFu) | (mhi << 16);
}

__global__ __launch_bounds__(THREADS)
void cll_pool_kernel(const float* __restrict__ in_feat,
                     const float* __restrict__ weights,
                     float* __restrict__ out,
                     int N, int M)
{
    const int t = threadIdx.x;
    const int lane = t & 31;
    const int warp = t >> 5;
    const int segbase = blockIdx.x * CHUNK + warp * SEG;   // this warp's first column

    // ---- one-time loads: this thread's 32 weights -> 16 packed negated pairs ----
    unsigned long long nwp[16];
    {
        const int g0 = segbase + lane * WPT;
        float wv[32];
        if (g0 + WPT <= M) {
            const float4* wp = reinterpret_cast<const float4*>(weights + g0);
            #pragma unroll
            for (int g = 0; g < 8; ++g) {
                float4 q = wp[g];
                wv[4*g+0] = q.x; wv[4*g+1] = q.y; wv[4*g+2] = q.z; wv[4*g+3] = q.w;
            }
        } else {
            #pragma unroll
            for (int b = 0; b < 32; ++b) {
                int gg = g0 + b;
                wv[b] = (gg < M) ? weights[gg] : OOR_VAL;
            }
        }
        #pragma unroll
        for (int k = 0; k < 16; ++k) {
            unsigned lo = __float_as_uint(-wv[2*k]);
            unsigned hi = __float_as_uint(-wv[2*k+1]);
            nwp[k] = ((unsigned long long)hi << 32) | lo;
        }
    }
    // per-lane halo weights for the warp's segment edges
    float hwl, hwr;
    {
        int gl = segbase - 32 + lane;          // cols [segbase-32, segbase)
        int gr = segbase + SEG + lane;         // cols [segbase+SEG, segbase+SEG+32)
        hwl = (gl >= 0 && gl < M) ? __ldg(weights + gl) : OOR_VAL;
        hwr = (gr < M)            ? __ldg(weights + gr) : OOR_VAL;
    }

    const unsigned long long c2 =
        ((unsigned long long)__float_as_uint(-0.01f) << 32) | __float_as_uint(-0.01f);

    const int row0 = blockIdx.y * ROWS_PER_BLOCK;

    // hoist all row inputs into registers (removes per-row LDG from chain head)
    float vrow[ROWS_PER_BLOCK];
    #pragma unroll
    for (int r = 0; r < ROWS_PER_BLOCK; ++r) {
        int i = row0 + r;
        vrow[r] = __ldg(&in_feat[(i < N) ? i : (N - 1)]);
    }

    const int shamt = (lane & 7) * 4;
    const int srcbase = lane >> 3;

    #pragma unroll 1
    for (int r = 0; r < ROWS_PER_BLOCK; ++r) {
        int i = row0 + r;
        if (i >= N) i = N - 1;
        const float vi = vrow[r];

        // ---- mask word + halo words (warp-local, no smem, no block sync) ----
        const unsigned long long vv =
            ((unsigned long long)__float_as_uint(vi) << 32) | __float_as_uint(vi);
        const unsigned m = mask32_sq(vv, nwp, c2);
        const unsigned hl = __ballot_sync(0xFFFFFFFFu, fabsf(vi - hwl) < THRESH);
        const unsigned hr = __ballot_sync(0xFFFFFFFFu, fabsf(vi - hwr) < THRESH);

        unsigned wm1 = __shfl_up_sync(0xFFFFFFFFu, m, 1);
        unsigned wp1 = __shfl_down_sync(0xFFFFFFFFu, m, 1);
        if (lane == 0)  wm1 = hl;
        if (lane == 31) wp1 = hr;

        // ---- width-51 sliding OR (radius 25) via log-step dilation ----
        unsigned long long lo = (unsigned long long)wm1 | ((unsigned long long)m << 32);
        unsigned long long hi = (unsigned long long)m   | ((unsigned long long)wp1 << 32);
        hi |= hi >> 1;  hi |= hi >> 2;  hi |= hi >> 4;  hi |= hi >> 8;  hi |= hi >> 10;
        lo |= lo << 1;  lo |= lo << 2;  lo |= lo << 4;  lo |= lo << 8;  lo |= lo << 10;
        const unsigned p = (unsigned)hi | (unsigned)(lo >> 32);

        // ---- dense coalesced emit: step s = 512B, lane offset 16B ----
        float* wout = out + (size_t)i * (size_t)M + segbase;
        #pragma unroll
        for (int s = 0; s < 8; ++s) {
            unsigned src = __shfl_sync(0xFFFFFFFFu, p, s * 4 + srcbase);
            unsigned bits = src >> shamt;
            float4 v;
            v.x = __uint_as_float((bits & 1u) * 0x3F800000u);
            v.y = __uint_as_float((bits & 2u) * 0x1FC00000u);
            v.z = __uint_as_float((bits & 4u) * 0x0FE00000u);
            v.w = __uint_as_float((bits & 8u) * 0x07F00000u);
            __stcs(reinterpret_cast<float4*>(wout + s * 128) + lane, v);
        }
    }
}

extern "C" void kernel_launch(void* const* d_in, const int* in_sizes, int n_in,
                              void* d_out, int out_size)
{
    const float* in_feat = (const float*)d_in[0];   // 1024 elements
    const float* weights = (const float*)d_in[1];   // 262144 elements
    float* out = (float*)d_out;

    const int N = in_sizes[0];
    const int M = in_sizes[1];

    dim3 grid((M + CHUNK - 1) / CHUNK, (N + ROWS_PER_BLOCK - 1) / ROWS_PER_BLOCK);
    cll_pool_kernel<<<grid, THREADS>>>(in_feat, weights, out, N, M);
}

// round 10
// speedup vs baseline: 1.4350x; 1.0646x over previous
#include <cuda_runtime.h>
#include <cuda_bf16.h>
#include <cstdint>

// pooled[i][j] = 1.0 if any k in [j-25, j+25] (in-range) has |in[i]-w[k]| < 0.1
// N=1024, M=262144 -> 1 GiB fp32 output; HBM write roofline target.
//
// R10 = R6 structure with WPT 32->16 to cut regs (~60 -> ~44) and unlock a
// 5th resident block per SM (32 -> 40 warps): more concurrent store streams
// to hide prologue gaps and feed the write queues.
//  - 16-bit mask words; radius-25 window spans +/-2 words -> 4 neighbor
//    shuffles + the same two 64-bit log-step dilations
//  - dense coalesced emit kept bit-identical to R6's proven pattern
//    (512B per warp step, lane*16B)
//  - R9's chain-split / vrow hoist reverted (measured regression)

#define THREADS 256
#define WPT 16                       // pooled bits per thread
#define SEG 512                      // columns per warp (32 lanes * 16)
#define CHUNK (THREADS * WPT)        // 4096 columns per block
#define ROWS_PER_BLOCK 8
#define THRESH 0.1f
#define OOR_VAL 3.0e38f              // sentinel == -inf pad (never within 0.1)

// mask bit b (0..15) = (vi - w[b])^2 < 0.01
__device__ __forceinline__ unsigned mask16_sq(unsigned long long vv,
                                              const unsigned long long* nwp,
                                              unsigned long long c2)
{
    unsigned m = 0;
    #pragma unroll
    for (int k = 7; k >= 0; --k) {
        unsigned long long d, s;
        asm("add.rn.f32x2 %0, %1, %2;" : "=l"(d) : "l"(vv), "l"(nwp[k]));
        asm("fma.rn.f32x2 %0, %1, %1, %2;" : "=l"(s) : "l"(d), "l"(c2));
        m = __funnelshift_l((unsigned)(s >> 32), m, 1);   // weight 2k+1
        m = __funnelshift_l((unsigned)s,         m, 1);   // weight 2k
    }
    return m & 0xFFFFu;              // bits [0,16): weight b in range
}

__global__ __launch_bounds__(THREADS, 5)
void cll_pool_kernel(const float* __restrict__ in_feat,
                     const float* __restrict__ weights,
                     float* __restrict__ out,
                     int N, int M)
{
    const int t = threadIdx.x;
    const int lane = t & 31;
    const int warp = t >> 5;
    const int segbase = blockIdx.x * CHUNK + warp * SEG;   // this warp's first column

    // ---- one-time loads: this thread's 16 weights -> 8 packed negated pairs ----
    unsigned long long nwp[8];
    {
        const int g0 = segbase + lane * WPT;
        float wv[16];
        if (g0 + WPT <= M) {
            const float4* wp = reinterpret_cast<const float4*>(weights + g0);
            #pragma unroll
            for (int g = 0; g < 4; ++g) {
                float4 q = wp[g];
                wv[4*g+0] = q.x; wv[4*g+1] = q.y; wv[4*g+2] = q.z; wv[4*g+3] = q.w;
            }
        } else {
            #pragma unroll
            for (int b = 0; b < 16; ++b) {
                int gg = g0 + b;
                wv[b] = (gg < M) ? weights[gg] : OOR_VAL;
            }
        }
        #pragma unroll
        for (int k = 0; k < 8; ++k) {
            unsigned lo = __float_as_uint(-wv[2*k]);
            unsigned hi = __float_as_uint(-wv[2*k+1]);
            nwp[k] = ((unsigned long long)hi << 32) | lo;
        }
    }
    // per-lane halo weights: 32 cols left of segment, 32 cols right
    float hwl, hwr;
    {
        int gl = segbase - 32 + lane;          // cols [segbase-32, segbase)
        int gr = segbase + SEG + lane;         // cols [segbase+SEG, segbase+SEG+32)
        hwl = (gl >= 0 && gl < M) ? __ldg(weights + gl) : OOR_VAL;
        hwr = (gr < M)            ? __ldg(weights + gr) : OOR_VAL;
    }

    const unsigned long long c2 =
        ((unsigned long long)__float_as_uint(-0.01f) << 32) | __float_as_uint(-0.01f);

    const int row0 = blockIdx.y * ROWS_PER_BLOCK;
    const int shamt = (lane & 3) * 4;          // nibble within 16-bit source word
    const int srcbase = lane >> 2;             // source lane offset within step

    #pragma unroll 1
    for (int r = 0; r < ROWS_PER_BLOCK; ++r) {
        int i = row0 + r;
        if (i >= N) i = N - 1;
        const float vi = __ldg(&in_feat[i]);

        // ---- mask word (16 bits) + halo words ----
        const unsigned long long vv =
            ((unsigned long long)__float_as_uint(vi) << 32) | __float_as_uint(vi);
        const unsigned m = mask16_sq(vv, nwp, c2);
        const unsigned hl = __ballot_sync(0xFFFFFFFFu, fabsf(vi - hwl) < THRESH);
        const unsigned hr = __ballot_sync(0xFFFFFFFFu, fabsf(vi - hwr) < THRESH);

        // neighbor 16-bit words: w[-2], w[-1], w[+1], w[+2]
        unsigned wm1 = __shfl_up_sync(0xFFFFFFFFu, m, 1);
        unsigned wm2 = __shfl_up_sync(0xFFFFFFFFu, m, 2);
        unsigned wp1 = __shfl_down_sync(0xFFFFFFFFu, m, 1);
        unsigned wp2 = __shfl_down_sync(0xFFFFFFFFu, m, 2);
        if (lane == 0) { wm1 = hl >> 16; wm2 = hl & 0xFFFFu; }
        if (lane == 1) { wm2 = hl >> 16; }
        if (lane == 31) { wp1 = hr & 0xFFFFu; wp2 = hr >> 16; }
        if (lane == 30) { wp2 = hr & 0xFFFFu; }

        // windows: lo = mask[base-32, base+32), hi = mask[base-16, base+48)
        unsigned long long lo =  (unsigned long long)wm2
                              | ((unsigned long long)wm1 << 16)
                              | ((unsigned long long)m   << 32)
                              | ((unsigned long long)wp1 << 48);
        unsigned long long hi =  (unsigned long long)wm1
                              | ((unsigned long long)m   << 16)
                              | ((unsigned long long)wp1 << 32)
                              | ((unsigned long long)wp2 << 48);

        // width-51 sliding OR (radius 25) via log-step dilation
        hi |= hi >> 1;  hi |= hi >> 2;  hi |= hi >> 4;  hi |= hi >> 8;  hi |= hi >> 10;
        lo |= lo << 1;  lo |= lo << 2;  lo |= lo << 4;  lo |= lo << 8;  lo |= lo << 10;
        // pooled bit t: lo'[t+32] covers [base+t-25, base+t]; hi'[t+16] covers [base+t, base+t+25]
        const unsigned p = ((unsigned)(lo >> 32) | (unsigned)(hi >> 16)) & 0xFFFFu;

        // ---- dense coalesced emit: 4 steps x 512B, lane offset 16B ----
        // step s: lane t writes cols s*128 + t*4; bits from lane (s*8 + t/4), nibble (t%4)
        float* wout = out + (size_t)i * (size_t)M + segbase;
        #pragma unroll
        for (int s = 0; s < 4; ++s) {
            unsigned src = __shfl_sync(0xFFFFFFFFu, p, s * 8 + srcbase);
            unsigned bits = src >> shamt;
            float4 v;
            v.x = __uint_as_float((bits & 1u) * 0x3F800000u);
            v.y = __uint_as_float((bits & 2u) * 0x1FC00000u);
            v.z = __uint_as_float((bits & 4u) * 0x0FE00000u);
            v.w = __uint_as_float((bits & 8u) * 0x07F00000u);
            __stcs(reinterpret_cast<float4*>(wout + s * 128) + lane, v);
        }
    }
}

extern "C" void kernel_launch(void* const* d_in, const int* in_sizes, int n_in,
                              void* d_out, int out_size)
{
    const float* in_feat = (const float*)d_in[0];   // 1024 elements
    const float* weights = (const float*)d_in[1];   // 262144 elements
    float* out = (float*)d_out;

    const int N = in_sizes[0];
    const int M = in_sizes[1];

    dim3 grid((M + CHUNK - 1) / CHUNK, (N + ROWS_PER_BLOCK - 1) / ROWS_PER_BLOCK);
    cll_pool_kernel<<<grid, THREADS>>>(in_feat, weights, out, N, M);
}

// round 11
// speedup vs baseline: 1.4375x; 1.0018x over previous
#include <cuda_runtime.h>
#include <cuda_bf16.h>
#include <cstdint>

// pooled[i][j] = 1.0 if any k in [j-25, j+25] (in-range) has |in[i]-w[k]| < 0.1
// N=1024, M=262144 -> 1 GiB fp32 output; HBM write roofline target.
//
// R11 = R10 (146.2us, DRAM 89%, L1 76.6%) + two-row packing:
// masks/pooled words are 16-bit, so two rows share one 32-bit register and
// ONE set of neighbor + emit shuffles -> SHFL per row halves (8->4),
// L1/MIO ops per row 13 -> ~9. Dilation, expansion, stores unchanged.

#define THREADS 256
#define WPT 16                       // pooled bits per thread
#define SEG 512                      // columns per warp
#define CHUNK (THREADS * WPT)        // 4096 columns per block
#define ROWS_PER_BLOCK 8
#define THRESH 0.1f
#define OOR_VAL 3.0e38f              // sentinel == -inf pad (never within 0.1)

// mask bit b (0..15) = (vi - w[b])^2 < 0.01
__device__ __forceinline__ unsigned mask16_sq(unsigned long long vv,
                                              const unsigned long long* nwp,
                                              unsigned long long c2)
{
    unsigned m = 0;
    #pragma unroll
    for (int k = 7; k >= 0; --k) {
        unsigned long long d, s;
        asm("add.rn.f32x2 %0, %1, %2;" : "=l"(d) : "l"(vv), "l"(nwp[k]));
        asm("fma.rn.f32x2 %0, %1, %1, %2;" : "=l"(s) : "l"(d), "l"(c2));
        m = __funnelshift_l((unsigned)(s >> 32), m, 1);   // weight 2k+1
        m = __funnelshift_l((unsigned)s,         m, 1);   // weight 2k
    }
    return m & 0xFFFFu;
}

__global__ __launch_bounds__(THREADS, 5)
void cll_pool_kernel(const float* __restrict__ in_feat,
                     const float* __restrict__ weights,
                     float* __restrict__ out,
                     int N, int M)
{
    const int t = threadIdx.x;
    const int lane = t & 31;
    const int warp = t >> 5;
    const int segbase = blockIdx.x * CHUNK + warp * SEG;

    // ---- one-time: this thread's 16 weights -> 8 packed negated pairs ----
    unsigned long long nwp[8];
    {
        const int g0 = segbase + lane * WPT;
        float wv[16];
        if (g0 + WPT <= M) {
            const float4* wp = reinterpret_cast<const float4*>(weights + g0);
            #pragma unroll
            for (int g = 0; g < 4; ++g) {
                float4 q = wp[g];
                wv[4*g+0] = q.x; wv[4*g+1] = q.y; wv[4*g+2] = q.z; wv[4*g+3] = q.w;
            }
        } else {
            #pragma unroll
            for (int b = 0; b < 16; ++b) {
                int gg = g0 + b;
                wv[b] = (gg < M) ? weights[gg] : OOR_VAL;
            }
        }
        #pragma unroll
        for (int k = 0; k < 8; ++k) {
            unsigned lo = __float_as_uint(-wv[2*k]);
            unsigned hi = __float_as_uint(-wv[2*k+1]);
            nwp[k] = ((unsigned long long)hi << 32) | lo;
        }
    }
    // per-lane halo weights (32 cols each side of segment)
    float hwl, hwr;
    {
        int gl = segbase - 32 + lane;
        int gr = segbase + SEG + lane;
        hwl = (gl >= 0 && gl < M) ? __ldg(weights + gl) : OOR_VAL;
        hwr = (gr < M)            ? __ldg(weights + gr) : OOR_VAL;
    }

    const unsigned long long c2 =
        ((unsigned long long)__float_as_uint(-0.01f) << 32) | __float_as_uint(-0.01f);

    const int row0 = blockIdx.y * ROWS_PER_BLOCK;
    const int shamt = (lane & 3) * 4;
    const int srcbase = lane >> 2;

    #pragma unroll 1
    for (int r = 0; r < ROWS_PER_BLOCK; r += 2) {
        int i0 = row0 + r;     if (i0 >= N) i0 = N - 1;
        int i1 = row0 + r + 1; if (i1 >= N) i1 = N - 1;
        const float v0 = __ldg(&in_feat[i0]);
        const float v1 = __ldg(&in_feat[i1]);

        // ---- two 16-bit mask words, packed ----
        const unsigned long long vv0 =
            ((unsigned long long)__float_as_uint(v0) << 32) | __float_as_uint(v0);
        const unsigned long long vv1 =
            ((unsigned long long)__float_as_uint(v1) << 32) | __float_as_uint(v1);
        const unsigned mm = mask16_sq(vv0, nwp, c2) | (mask16_sq(vv1, nwp, c2) << 16);

        const unsigned hl0 = __ballot_sync(0xFFFFFFFFu, fabsf(v0 - hwl) < THRESH);
        const unsigned hr0 = __ballot_sync(0xFFFFFFFFu, fabsf(v0 - hwr) < THRESH);
        const unsigned hl1 = __ballot_sync(0xFFFFFFFFu, fabsf(v1 - hwl) < THRESH);
        const unsigned hr1 = __ballot_sync(0xFFFFFFFFu, fabsf(v1 - hwr) < THRESH);

        // ---- ONE set of neighbor shuffles for both rows ----
        unsigned wm1 = __shfl_up_sync(0xFFFFFFFFu, mm, 1);
        unsigned wm2 = __shfl_up_sync(0xFFFFFFFFu, mm, 2);
        unsigned wp1 = __shfl_down_sync(0xFFFFFFFFu, mm, 1);
        unsigned wp2 = __shfl_down_sync(0xFFFFFFFFu, mm, 2);
        if (lane == 0) {
            wm1 = (hl0 >> 16) | (hl1 & 0xFFFF0000u);
            wm2 = (hl0 & 0xFFFFu) | (hl1 << 16);
        }
        if (lane == 1)  { wm2 = (hl0 >> 16) | (hl1 & 0xFFFF0000u); }
        if (lane == 31) {
            wp1 = (hr0 & 0xFFFFu) | (hr1 << 16);
            wp2 = (hr0 >> 16) | (hr1 & 0xFFFF0000u);
        }
        if (lane == 30) { wp2 = (hr0 & 0xFFFFu) | (hr1 << 16); }

        // ---- per-row dilation (unchanged math), pooled words packed ----
        unsigned pp = 0;
        #pragma unroll
        for (int x = 0; x < 2; ++x) {
            const unsigned a2 = (wm2 >> (16 * x)) & 0xFFFFu;
            const unsigned a1 = (wm1 >> (16 * x)) & 0xFFFFu;
            const unsigned a0 = (mm  >> (16 * x)) & 0xFFFFu;
            const unsigned b1 = (wp1 >> (16 * x)) & 0xFFFFu;
            const unsigned b2 = (wp2 >> (16 * x)) & 0xFFFFu;
            unsigned long long lo =  (unsigned long long)a2
                                  | ((unsigned long long)a1 << 16)
                                  | ((unsigned long long)a0 << 32)
                                  | ((unsigned long long)b1 << 48);
            unsigned long long hi =  (unsigned long long)a1
                                  | ((unsigned long long)a0 << 16)
                                  | ((unsigned long long)b1 << 32)
                                  | ((unsigned long long)b2 << 48);
            hi |= hi >> 1;  hi |= hi >> 2;  hi |= hi >> 4;  hi |= hi >> 8;  hi |= hi >> 10;
            lo |= lo << 1;  lo |= lo << 2;  lo |= lo << 4;  lo |= lo << 8;  lo |= lo << 10;
            const unsigned p = ((unsigned)(lo >> 32) | (unsigned)(hi >> 16)) & 0xFFFFu;
            pp |= p << (16 * x);
        }

        // ---- emit: ONE set of 4 shuffles feeds both rows' dense stores ----
        float* w0 = out + (size_t)i0 * (size_t)M + segbase;
        float* w1 = out + (size_t)i1 * (size_t)M + segbase;
        #pragma unroll
        for (int s = 0; s < 4; ++s) {
            const unsigned src = __shfl_sync(0xFFFFFFFFu, pp, s * 8 + srcbase);
            const unsigned b0 = src >> shamt;          // row i0 nibble
            const unsigned b1 = src >> (shamt + 16);   // row i1 nibble
            float4 q0, q1;
            q0.x = __uint_as_float((b0 & 1u) * 0x3F800000u);
            q0.y = __uint_as_float((b0 & 2u) * 0x1FC00000u);
            q0.z = __uint_as_float((b0 & 4u) * 0x0FE00000u);
            q0.w = __uint_as_float((b0 & 8u) * 0x07F00000u);
            q1.x = __uint_as_float((b1 & 1u) * 0x3F800000u);
            q1.y = __uint_as_float((b1 & 2u) * 0x1FC00000u);
            q1.z = __uint_as_float((b1 & 4u) * 0x0FE00000u);
            q1.w = __uint_as_float((b1 & 8u) * 0x07F00000u);
            __stcs(reinterpret_cast<float4*>(w0 + s * 128) + lane, q0);
            __stcs(reinterpret_cast<float4*>(w1 + s * 128) + lane, q1);
        }
    }
}

extern "C" void kernel_launch(void* const* d_in, const int* in_sizes, int n_in,
                              void* d_out, int out_size)
{
    const float* in_feat = (const float*)d_in[0];   // 1024 elements
    const float* weights = (const float*)d_in[1];   // 262144 elements
    float* out = (float*)d_out;

    const int N = in_sizes[0];
    const int M = in_sizes[1];

    dim3 grid((M + CHUNK - 1) / CHUNK, (N + ROWS_PER_BLOCK - 1) / ROWS_PER_BLOCK);
    cll_pool_kernel<<<grid, THREADS>>>(in_feat, weights, out, N, M);
}